// round 2
// baseline (speedup 1.0000x reference)
#include <cuda_runtime.h>
#include <cstdint>

// Scratch: per-node best key = (ordered(t) << 32) | (pos + 1). 0 == empty.
static __device__ unsigned long long g_best[1 << 20];
static __device__ int g_idx_is_32;  // 1 if index buffer is int32, 0 if int64

__global__ void init_best_kernel(int n) {
    int i = blockIdx.x * blockDim.x + threadIdx.x;
    if (i == 0) g_idx_is_32 = 0;
    if (i < n) g_best[i] = 0ull;
}

// Detect index dtype: view buffer as int32. For int64 values < 2^31, every odd
// 32-bit word is the (zero) high half. For int32 data, odd words are real
// indices (uniform in [0,1e5) -> nonzero w.p. ~1). Scan 512 odd words.
__global__ void detect_idx_kernel(const int* __restrict__ idx32, int E) {
    int tid = threadIdx.x;
    int nwords = 2 * E;  // total int32 words available under EITHER dtype >= 2*E? 
    // int32 buffer has E words; int64 buffer has 2E words. Only read < E words
    // to be safe under both interpretations.
    int limit = E;  // words we may safely touch
    int found = 0;
    for (int i = tid; i < 512; i += blockDim.x) {
        int w = 2 * i + 1;
        if (w < limit && idx32[w] != 0) found = 1;
    }
    if (__syncthreads_or(found)) {
        if (tid == 0) g_idx_is_32 = 1;
    }
    (void)nwords;
}

// Map float bits to an order-preserving unsigned int (for non-NaN floats).
__device__ __forceinline__ unsigned int order_f32(float f) {
    unsigned int b = __float_as_uint(f);
    return (b & 0x80000000u) ? ~b : (b | 0x80000000u);
}

__global__ void scatter_kernel(const void* __restrict__ index_raw,
                               const float* __restrict__ t, int E, int N) {
    int e = blockIdx.x * blockDim.x + threadIdx.x;
    if (e >= E) return;
    long long idx;
    if (g_idx_is_32) {
        idx = (long long)((const int*)index_raw)[e];
    } else {
        idx = ((const long long*)index_raw)[e];
    }
    if (idx < 0 || idx >= N) return;  // hard guard: never fault
    unsigned int u = order_f32(t[e]);
    unsigned long long key = ((unsigned long long)u << 32) | (unsigned int)(e + 1);
    atomicMax(&g_best[(int)idx], key);
}

// One warp per node. D4 = D/4 float4 elements per row (D=128 -> 32, one per lane).
__global__ void gather_kernel(const float4* __restrict__ msg,
                              float4* __restrict__ out, int N, int D4, int E) {
    int warp = (blockIdx.x * blockDim.x + threadIdx.x) >> 5;
    int lane = threadIdx.x & 31;
    if (warp >= N) return;
    unsigned long long key = g_best[warp];  // broadcast read
    size_t obase = (size_t)warp * D4;
    long long e = (long long)((unsigned int)key) - 1;
    if (key == 0ull || e >= E) {
        float4 z = make_float4(0.f, 0.f, 0.f, 0.f);
        for (int j = lane; j < D4; j += 32) out[obase + j] = z;
    } else {
        size_t ibase = (size_t)e * D4;
        for (int j = lane; j < D4; j += 32) out[obase + j] = msg[ibase + j];
    }
}

__global__ void gather_kernel_scalar(const float* __restrict__ msg,
                                     float* __restrict__ out, int N, int D, int E) {
    int warp = (blockIdx.x * blockDim.x + threadIdx.x) >> 5;
    int lane = threadIdx.x & 31;
    if (warp >= N) return;
    unsigned long long key = g_best[warp];
    size_t obase = (size_t)warp * D;
    long long e = (long long)((unsigned int)key) - 1;
    if (key == 0ull || e >= E) {
        for (int j = lane; j < D; j += 32) out[obase + j] = 0.f;
    } else {
        size_t ibase = (size_t)e * (size_t)D;
        for (int j = lane; j < D; j += 32) out[obase + j] = msg[ibase + j];
    }
}

extern "C" void kernel_launch(void* const* d_in, const int* in_sizes, int n_in,
                              void* d_out, int out_size) {
    const float* msg   = (const float*)d_in[0];  // [E, D] float32
    const void*  index = d_in[1];                // [E] int32 or int64
    const float* t     = (const float*)d_in[2];  // [E] float32

    int E = in_sizes[2];
    int D = in_sizes[0] / E;
    int N = out_size / D;
    if (N > (1 << 20)) N = (1 << 20);  // scratch capacity guard

    // 1) init per-node best keys (+ reset dtype flag)
    {
        int threads = 256;
        int blocks = (N + threads - 1) / threads;
        init_best_kernel<<<blocks, threads>>>(N);
    }
    // 2) detect index dtype (reads only first E int32 words: safe either way)
    detect_idx_kernel<<<1, 256>>>((const int*)index, E);
    // 3) atomic lexicographic-max scatter over events
    {
        int threads = 256;
        int blocks = (E + threads - 1) / threads;
        scatter_kernel<<<blocks, threads>>>(index, t, E, N);
    }
    // 4) gather winning rows (one warp per node)
    {
        int threads = 256;  // 8 warps/block
        int warps_per_block = threads / 32;
        int blocks = (N + warps_per_block - 1) / warps_per_block;
        if ((D & 3) == 0) {
            gather_kernel<<<blocks, threads>>>((const float4*)msg, (float4*)d_out,
                                               N, D >> 2, E);
        } else {
            gather_kernel_scalar<<<blocks, threads>>>(msg, (float*)d_out, N, D, E);
        }
    }
}

// round 3
// speedup vs baseline: 1.1156x; 1.1156x over previous
#include <cuda_runtime.h>
#include <cstdint>

// Scratch: per-node best key = (ordered(t) << 32) | (pos + 1). 0 == empty.
static __device__ unsigned long long g_best[1 << 20];
static __device__ int g_idx_is_32;  // 1 if index buffer is int32, 0 if int64

// Init scratch + detect index dtype (block 0). For int64 values < 2^31 every
// odd 32-bit word is zero; for int32 data odd words are real indices.
__global__ void init_kernel(int n, const int* __restrict__ idx32, int E) {
    int i = blockIdx.x * blockDim.x + threadIdx.x;
    if (i < n) g_best[i] = 0ull;
    if (blockIdx.x == 0) {
        int found = 0;
        for (int j = threadIdx.x; j < 512; j += blockDim.x) {
            int w = 2 * j + 1;
            if (w < E && idx32[w] != 0) found = 1;  // only reads < E words: safe
        }
        found = __syncthreads_or(found);
        if (threadIdx.x == 0) g_idx_is_32 = found;
    }
}

// Map float bits to an order-preserving unsigned int (for non-NaN floats).
__device__ __forceinline__ unsigned int order_f32(float f) {
    unsigned int b = __float_as_uint(f);
    return (b & 0x80000000u) ? ~b : (b | 0x80000000u);
}

// 4 events per thread: vector loads of t, fewer issue slots per atomic.
__global__ void scatter_kernel(const void* __restrict__ index_raw,
                               const float* __restrict__ t, int E, int N) {
    int base = (blockIdx.x * blockDim.x + threadIdx.x) * 4;
    if (base >= E) return;
    int is32 = g_idx_is_32;
    int cnt = min(4, E - base);
#pragma unroll
    for (int k = 0; k < 4; k++) {
        if (k >= cnt) break;
        int e = base + k;
        long long idx = is32 ? (long long)((const int*)index_raw)[e]
                             : ((const long long*)index_raw)[e];
        if (idx < 0 || idx >= N) continue;  // hard guard: never fault
        unsigned long long key =
            ((unsigned long long)order_f32(t[e]) << 32) | (unsigned int)(e + 1);
        atomicMax(&g_best[(int)idx], key);
    }
}

// Fast gather for D==128: each warp handles 4 nodes; every thread issues 4
// INDEPENDENT LDG.128 before any store (MLP=4 to hide DRAM latency).
__global__ void gather_kernel_d128(const float4* __restrict__ msg,
                                   float4* __restrict__ out, int N, int E) {
    int lane = threadIdx.x & 31;
    int warp = (blockIdx.x * blockDim.x + threadIdx.x) >> 5;
    int n0 = warp * 4;
    if (n0 >= N) return;

    unsigned long long mykey = 0ull;
    if (lane < 4 && (n0 + lane) < N) mykey = g_best[n0 + lane];

    float4 v[4];
#pragma unroll
    for (int k = 0; k < 4; k++) {
        unsigned long long key = __shfl_sync(0xffffffffu, mykey, k);
        long long e = (long long)((unsigned int)key) - 1;
        if (key != 0ull && e < (long long)E && (n0 + k) < N) {
            v[k] = msg[(size_t)e * 32 + lane];
        } else {
            v[k] = make_float4(0.f, 0.f, 0.f, 0.f);
        }
    }
#pragma unroll
    for (int k = 0; k < 4; k++) {
        if ((n0 + k) < N) out[(size_t)(n0 + k) * 32 + lane] = v[k];
    }
}

// Generic fallback: one warp per node, float4 strided.
__global__ void gather_kernel_generic(const float* __restrict__ msg,
                                      float* __restrict__ out, int N, int D, int E) {
    int warp = (blockIdx.x * blockDim.x + threadIdx.x) >> 5;
    int lane = threadIdx.x & 31;
    if (warp >= N) return;
    unsigned long long key = g_best[warp];
    size_t obase = (size_t)warp * D;
    long long e = (long long)((unsigned int)key) - 1;
    if (key == 0ull || e >= (long long)E) {
        for (int j = lane; j < D; j += 32) out[obase + j] = 0.f;
    } else {
        size_t ibase = (size_t)e * (size_t)D;
        for (int j = lane; j < D; j += 32) out[obase + j] = msg[ibase + j];
    }
}

extern "C" void kernel_launch(void* const* d_in, const int* in_sizes, int n_in,
                              void* d_out, int out_size) {
    const float* msg   = (const float*)d_in[0];  // [E, D] float32
    const void*  index = d_in[1];                // [E] int32 or int64
    const float* t     = (const float*)d_in[2];  // [E] float32

    int E = in_sizes[2];
    int D = in_sizes[0] / E;
    int N = out_size / D;
    if (N > (1 << 20)) N = (1 << 20);  // scratch capacity guard

    // 1) init per-node best keys + dtype detect (fused)
    {
        int threads = 256;
        int blocks = (N + threads - 1) / threads;
        init_kernel<<<blocks, threads>>>(N, (const int*)index, E);
    }
    // 2) atomic lexicographic-max scatter, 4 events/thread
    {
        int threads = 256;
        int elems_per_block = threads * 4;
        int blocks = (E + elems_per_block - 1) / elems_per_block;
        scatter_kernel<<<blocks, threads>>>(index, t, E, N);
    }
    // 3) gather winning rows
    if (D == 128) {
        int threads = 256;                       // 8 warps * 4 nodes = 32 nodes/blk
        int nodes_per_block = (threads / 32) * 4;
        int blocks = (N + nodes_per_block - 1) / nodes_per_block;
        gather_kernel_d128<<<blocks, threads>>>((const float4*)msg,
                                                (float4*)d_out, N, E);
    } else {
        int threads = 256;
        int warps_per_block = threads / 32;
        int blocks = (N + warps_per_block - 1) / warps_per_block;
        gather_kernel_generic<<<blocks, threads>>>(msg, (float*)d_out, N, D, E);
    }
}

// round 4
// speedup vs baseline: 1.3645x; 1.2231x over previous
#include <cuda_runtime.h>
#include <cstdint>

// Scratch: per-node best key = (ordered(t) << 32) | (pos + 1). 0 == empty.
static __device__ unsigned long long g_best[1 << 20];
static __device__ int g_idx_is_32;  // 1 if index buffer is int32, 0 if int64

// Init scratch + detect index dtype (block 0). For int64 values < 2^31 every
// odd 32-bit word is zero; for int32 data odd words are real indices.
__global__ void init_kernel(int n, const int* __restrict__ idx32, int E) {
    int i = blockIdx.x * blockDim.x + threadIdx.x;
    if (i < n) g_best[i] = 0ull;
    if (blockIdx.x == 0) {
        int found = 0;
        for (int j = threadIdx.x; j < 512; j += blockDim.x) {
            int w = 2 * j + 1;
            if (w < E && idx32[w] != 0) found = 1;  // only reads < E words: safe
        }
        found = __syncthreads_or(found);
        if (threadIdx.x == 0) g_idx_is_32 = found;
    }
}

// Map float bits to an order-preserving unsigned int (for non-NaN floats).
__device__ __forceinline__ unsigned int order_f32(float f) {
    unsigned int b = __float_as_uint(f);
    return (b & 0x80000000u) ? ~b : (b | 0x80000000u);
}

// 4 events per thread: vector loads of t, fewer issue slots per atomic.
__global__ void scatter_kernel(const void* __restrict__ index_raw,
                               const float* __restrict__ t, int E, int N) {
    int base = (blockIdx.x * blockDim.x + threadIdx.x) * 4;
    if (base >= E) return;
    int is32 = g_idx_is_32;
    int cnt = min(4, E - base);
#pragma unroll
    for (int k = 0; k < 4; k++) {
        if (k >= cnt) break;
        int e = base + k;
        long long idx = is32 ? (long long)((const int*)index_raw)[e]
                             : ((const long long*)index_raw)[e];
        if (idx < 0 || idx >= N) continue;  // hard guard: never fault
        unsigned long long key =
            ((unsigned long long)order_f32(t[e]) << 32) | (unsigned int)(e + 1);
        atomicMax(&g_best[(int)idx], key);
    }
}

// Fast gather for D==128: each warp handles 4 nodes; every thread issues 4
// INDEPENDENT LDG.128 before any store (MLP=4 to hide DRAM latency).
__global__ void gather_kernel_d128(const float4* __restrict__ msg,
                                   float4* __restrict__ out, int N, int E) {
    int lane = threadIdx.x & 31;
    int warp = (blockIdx.x * blockDim.x + threadIdx.x) >> 5;
    int n0 = warp * 4;
    if (n0 >= N) return;

    unsigned long long mykey = 0ull;
    if (lane < 4 && (n0 + lane) < N) mykey = g_best[n0 + lane];

    float4 v[4];
#pragma unroll
    for (int k = 0; k < 4; k++) {
        unsigned long long key = __shfl_sync(0xffffffffu, mykey, k);
        long long e = (long long)((unsigned int)key) - 1;
        if (key != 0ull && e < (long long)E && (n0 + k) < N) {
            v[k] = msg[(size_t)e * 32 + lane];
        } else {
            v[k] = make_float4(0.f, 0.f, 0.f, 0.f);
        }
    }
#pragma unroll
    for (int k = 0; k < 4; k++) {
        if ((n0 + k) < N) out[(size_t)(n0 + k) * 32 + lane] = v[k];
    }
}

// Generic fallback: one warp per node, float4 strided.
__global__ void gather_kernel_generic(const float* __restrict__ msg,
                                      float* __restrict__ out, int N, int D, int E) {
    int warp = (blockIdx.x * blockDim.x + threadIdx.x) >> 5;
    int lane = threadIdx.x & 31;
    if (warp >= N) return;
    unsigned long long key = g_best[warp];
    size_t obase = (size_t)warp * D;
    long long e = (long long)((unsigned int)key) - 1;
    if (key == 0ull || e >= (long long)E) {
        for (int j = lane; j < D; j += 32) out[obase + j] = 0.f;
    } else {
        size_t ibase = (size_t)e * (size_t)D;
        for (int j = lane; j < D; j += 32) out[obase + j] = msg[ibase + j];
    }
}

extern "C" void kernel_launch(void* const* d_in, const int* in_sizes, int n_in,
                              void* d_out, int out_size) {
    const float* msg   = (const float*)d_in[0];  // [E, D] float32
    const void*  index = d_in[1];                // [E] int32 or int64
    const float* t     = (const float*)d_in[2];  // [E] float32

    int E = in_sizes[2];
    int D = in_sizes[0] / E;
    int N = out_size / D;
    if (N > (1 << 20)) N = (1 << 20);  // scratch capacity guard

    // 1) init per-node best keys + dtype detect (fused)
    {
        int threads = 256;
        int blocks = (N + threads - 1) / threads;
        init_kernel<<<blocks, threads>>>(N, (const int*)index, E);
    }
    // 2) atomic lexicographic-max scatter, 4 events/thread
    {
        int threads = 256;
        int elems_per_block = threads * 4;
        int blocks = (E + elems_per_block - 1) / elems_per_block;
        scatter_kernel<<<blocks, threads>>>(index, t, E, N);
    }
    // 3) gather winning rows
    if (D == 128) {
        int threads = 256;                       // 8 warps * 4 nodes = 32 nodes/blk
        int nodes_per_block = (threads / 32) * 4;
        int blocks = (N + nodes_per_block - 1) / nodes_per_block;
        gather_kernel_d128<<<blocks, threads>>>((const float4*)msg,
                                                (float4*)d_out, N, E);
    } else {
        int threads = 256;
        int warps_per_block = threads / 32;
        int blocks = (N + warps_per_block - 1) / warps_per_block;
        gather_kernel_generic<<<blocks, threads>>>(msg, (float*)d_out, N, D, E);
    }
}

// round 5
// speedup vs baseline: 1.4917x; 1.0932x over previous
#include <cuda_runtime.h>
#include <cstdint>

// Scratch: per-node best key = (ordered(t) << 32) | (pos + 1). 0 == empty.
__device__ unsigned long long g_best[1 << 20];

// Map float bits to an order-preserving unsigned int (for non-NaN floats).
__device__ __forceinline__ unsigned int order_f32(float f) {
    unsigned int b = __float_as_uint(f);
    return (b & 0x80000000u) ? ~b : (b | 0x80000000u);
}

// Scatter with inline index-dtype detection.
// Detection: view buffer as int32. For int64 values < 2^31 every odd 32-bit
// word is the zero high half; for int32 data odd words are real indices
// (uniform in [0,1e5), all-zero over 256 samples has prob ~1e-1280).
__global__ void scatter_kernel(const void* __restrict__ index_raw,
                               const float* __restrict__ t, int E, int N) {
    // per-block dtype vote (reads only words < E: safe under either dtype)
    const int* idx32 = (const int*)index_raw;
    int w = 2 * threadIdx.x + 1;
    int found = (w < E && idx32[w] != 0) ? 1 : 0;
    int is32 = __syncthreads_or(found);

    int base = (blockIdx.x * blockDim.x + threadIdx.x) * 4;
    if (base >= E) return;
    int cnt = min(4, E - base);

    if (is32 && cnt == 4) {
        // vectorized path: int4 indices + float4 timestamps
        int4 idx = *(const int4*)(idx32 + base);
        float4 tv = *(const float4*)(t + base);
        int ix[4] = {idx.x, idx.y, idx.z, idx.w};
        float tt[4] = {tv.x, tv.y, tv.z, tv.w};
#pragma unroll
        for (int k = 0; k < 4; k++) {
            if (ix[k] < 0 || ix[k] >= N) continue;
            unsigned long long key =
                ((unsigned long long)order_f32(tt[k]) << 32) |
                (unsigned int)(base + k + 1);
            atomicMax(&g_best[ix[k]], key);
        }
    } else {
#pragma unroll
        for (int k = 0; k < 4; k++) {
            if (k >= cnt) break;
            int e = base + k;
            long long idx = is32 ? (long long)idx32[e]
                                 : ((const long long*)index_raw)[e];
            if (idx < 0 || idx >= N) continue;
            unsigned long long key =
                ((unsigned long long)order_f32(t[e]) << 32) |
                (unsigned int)(e + 1);
            atomicMax(&g_best[(int)idx], key);
        }
    }
}

// Fast gather for D==128: each warp handles 8 nodes; every thread issues 8
// INDEPENDENT LDG.128 before any store (MLP=8 to hide DRAM latency).
__global__ void gather_kernel_d128(const float4* __restrict__ msg,
                                   float4* __restrict__ out, int N, int E) {
    int lane = threadIdx.x & 31;
    int warp = (blockIdx.x * blockDim.x + threadIdx.x) >> 5;
    int n0 = warp * 8;
    if (n0 >= N) return;

    unsigned long long mykey = 0ull;
    if (lane < 8 && (n0 + lane) < N) mykey = g_best[n0 + lane];

    float4 v[8];
#pragma unroll
    for (int k = 0; k < 8; k++) {
        unsigned long long key = __shfl_sync(0xffffffffu, mykey, k);
        long long e = (long long)((unsigned int)key) - 1;
        if (key != 0ull && e < (long long)E && (n0 + k) < N) {
            v[k] = msg[(size_t)e * 32 + lane];
        } else {
            v[k] = make_float4(0.f, 0.f, 0.f, 0.f);
        }
    }
#pragma unroll
    for (int k = 0; k < 8; k++) {
        if ((n0 + k) < N) out[(size_t)(n0 + k) * 32 + lane] = v[k];
    }
}

// Generic fallback: one warp per node, scalar strided.
__global__ void gather_kernel_generic(const float* __restrict__ msg,
                                      float* __restrict__ out, int N, int D, int E) {
    int warp = (blockIdx.x * blockDim.x + threadIdx.x) >> 5;
    int lane = threadIdx.x & 31;
    if (warp >= N) return;
    unsigned long long key = g_best[warp];
    size_t obase = (size_t)warp * D;
    long long e = (long long)((unsigned int)key) - 1;
    if (key == 0ull || e >= (long long)E) {
        for (int j = lane; j < D; j += 32) out[obase + j] = 0.f;
    } else {
        size_t ibase = (size_t)e * (size_t)D;
        for (int j = lane; j < D; j += 32) out[obase + j] = msg[ibase + j];
    }
}

extern "C" void kernel_launch(void* const* d_in, const int* in_sizes, int n_in,
                              void* d_out, int out_size) {
    const float* msg   = (const float*)d_in[0];  // [E, D] float32
    const void*  index = d_in[1];                // [E] int32 or int64
    const float* t     = (const float*)d_in[2];  // [E] float32

    int E = in_sizes[2];
    int D = in_sizes[0] / E;
    int N = out_size / D;
    if (N > (1 << 20)) N = (1 << 20);  // scratch capacity guard

    // 1) zero per-node best keys via memset node (full-BW, no kernel latency)
    void* best_ptr = nullptr;
    cudaGetSymbolAddress(&best_ptr, g_best);
    cudaMemsetAsync(best_ptr, 0, (size_t)N * sizeof(unsigned long long), 0);

    // 2) atomic lexicographic-max scatter (inline dtype detect), 4 events/thread
    {
        int threads = 256;
        int elems_per_block = threads * 4;
        int blocks = (E + elems_per_block - 1) / elems_per_block;
        scatter_kernel<<<blocks, threads>>>(index, t, E, N);
    }

    // 3) gather winning rows
    if (D == 128) {
        int threads = 256;                        // 8 warps * 8 nodes = 64 nodes/blk
        int nodes_per_block = (threads / 32) * 8;
        int blocks = (N + nodes_per_block - 1) / nodes_per_block;
        gather_kernel_d128<<<blocks, threads>>>((const float4*)msg,
                                                (float4*)d_out, N, E);
    } else {
        int threads = 256;
        int warps_per_block = threads / 32;
        int blocks = (N + warps_per_block - 1) / warps_per_block;
        gather_kernel_generic<<<blocks, threads>>>(msg, (float*)d_out, N, D, E);
    }
}